// round 2
// baseline (speedup 1.0000x reference)
#include <cuda_runtime.h>
#include <cuda_bf16.h>
#include <stdint.h>

// Problem constants (fixed by the dataset)
#define N_NODES 100000
#define E_EDGES 1600000
#define DIN 128
#define HID 64
#define DOUT 2

// Scratch in device globals (no allocation allowed)
__device__ float g_agg0[(size_t)N_NODES * DIN];   // layer-0 aggregation sums
__device__ float g_agg1[(size_t)N_NODES * HID];   // layer-1 aggregation sums
__device__ float g_h[(size_t)N_NODES * HID];      // hidden activations
__device__ float g_cnt[N_NODES];                  // per-dst edge counts (shared by both layers)

// ---------------------------------------------------------------------------
// Layer 0 scatter: one warp per edge. 128 channels = 32 lanes x float4.
// msg = x[src] * env_attr[e]; atomicAdd into agg0[dst]; lane0 counts.
// ---------------------------------------------------------------------------
__global__ void scatter0_kernel(const float* __restrict__ x,
                                const int* __restrict__ ei,
                                const float* __restrict__ ea,
                                float* __restrict__ agg0,
                                float* __restrict__ cnt,
                                int E)
{
    int warp = (blockIdx.x * blockDim.x + threadIdx.x) >> 5;
    int lane = threadIdx.x & 31;
    if (warp >= E) return;

    int s = ei[warp];
    int d = ei[E + warp];

    const float4* xr = reinterpret_cast<const float4*>(x + (long long)s * DIN);
    const float4* er = reinterpret_cast<const float4*>(ea + (long long)warp * DIN);
    float4 xv = xr[lane];
    float4 ev = er[lane];

    float* out = agg0 + (long long)d * DIN + lane * 4;
    atomicAdd(out + 0, xv.x * ev.x);
    atomicAdd(out + 1, xv.y * ev.y);
    atomicAdd(out + 2, xv.z * ev.z);
    atomicAdd(out + 3, xv.w * ev.w);

    if (lane == 0) atomicAdd(cnt + d, 1.0f);
}

// ---------------------------------------------------------------------------
// Layer 0 dense: h = relu(concat(x, agg0/cnt) @ W0 + b0)
// W0 [256,64] staged in smem; 256 threads = 4 node-slots x 64 out channels.
// ---------------------------------------------------------------------------
__global__ void layer0_mm_kernel(const float* __restrict__ x,
                                 const float* __restrict__ agg0,
                                 const float* __restrict__ cnt,
                                 const float* __restrict__ W0,
                                 const float* __restrict__ b0,
                                 float* __restrict__ h,
                                 int N)
{
    extern __shared__ float sm[];
    float* sW = sm;                 // 256*64
    float* sF = sm + 2 * DIN * HID; // 4*256

    for (int i = threadIdx.x; i < 2 * DIN * HID; i += blockDim.x)
        sW[i] = W0[i];
    __syncthreads();

    int slot = threadIdx.x >> 6;   // 0..3
    int oc   = threadIdx.x & 63;   // output channel
    float bias = b0[oc];

    for (int base = blockIdx.x * 4; base < N; base += gridDim.x * 4) {
        __syncthreads();
        // cooperatively stage 4 nodes x 256 input features
        for (int i = threadIdx.x; i < 4 * 2 * DIN; i += blockDim.x) {
            int nn = base + (i >> 8);
            int k  = i & 255;
            float v = 0.f;
            if (nn < N) {
                if (k < DIN) {
                    v = x[(long long)nn * DIN + k];
                } else {
                    float c = cnt[nn];
                    c = c < 1.f ? 1.f : c;
                    v = agg0[(long long)nn * DIN + (k - DIN)] * (1.0f / c);
                }
            }
            sF[i] = v;
        }
        __syncthreads();

        int node = base + slot;
        if (node < N) {
            const float* f = sF + slot * 2 * DIN;
            float acc = bias;
            #pragma unroll 8
            for (int k = 0; k < 2 * DIN; k++)
                acc = fmaf(f[k], sW[k * HID + oc], acc);
            h[(long long)node * HID + oc] = acc > 0.f ? acc : 0.f;
        }
    }
}

// ---------------------------------------------------------------------------
// Layer 1 scatter: one warp per edge. 64 channels = 32 lanes x float2.
// ---------------------------------------------------------------------------
__global__ void scatter1_kernel(const float* __restrict__ h,
                                const int* __restrict__ ei,
                                const float* __restrict__ ea,
                                float* __restrict__ agg1,
                                int E)
{
    int warp = (blockIdx.x * blockDim.x + threadIdx.x) >> 5;
    int lane = threadIdx.x & 31;
    if (warp >= E) return;

    int s = ei[warp];
    int d = ei[E + warp];

    const float2* hr = reinterpret_cast<const float2*>(h + (long long)s * HID);
    const float2* er = reinterpret_cast<const float2*>(ea + (long long)warp * HID);
    float2 hv = hr[lane];
    float2 ev = er[lane];

    float* out = agg1 + (long long)d * HID + lane * 2;
    atomicAdd(out + 0, hv.x * ev.x);
    atomicAdd(out + 1, hv.y * ev.y);
}

// ---------------------------------------------------------------------------
// Layer 1 dense: out = concat(h, agg1/cnt) @ W1 + b1, one warp per node.
// W1 [128,2], lane l covers input channels {l, l+32} of each half.
// ---------------------------------------------------------------------------
__global__ void layer1_mm_kernel(const float* __restrict__ h,
                                 const float* __restrict__ agg1,
                                 const float* __restrict__ cnt,
                                 const float* __restrict__ W1,
                                 const float* __restrict__ b1,
                                 float* __restrict__ out,
                                 int N)
{
    __shared__ float sW[2 * HID * DOUT]; // 256
    __shared__ float sb[DOUT];
    for (int i = threadIdx.x; i < 2 * HID * DOUT; i += blockDim.x) sW[i] = W1[i];
    if (threadIdx.x < DOUT) sb[threadIdx.x] = b1[threadIdx.x];
    __syncthreads();

    int warp = (blockIdx.x * blockDim.x + threadIdx.x) >> 5;
    int lane = threadIdx.x & 31;
    if (warp >= N) return;

    float c = cnt[warp];
    float inv = 1.0f / (c < 1.f ? 1.f : c);

    long long rb = (long long)warp * HID;
    float h0 = h[rb + lane];
    float h1 = h[rb + 32 + lane];
    float a0 = agg1[rb + lane] * inv;
    float a1 = agg1[rb + 32 + lane] * inv;

    float acc0 = h0 * sW[lane * 2 + 0] + h1 * sW[(32 + lane) * 2 + 0]
               + a0 * sW[(64 + lane) * 2 + 0] + a1 * sW[(96 + lane) * 2 + 0];
    float acc1 = h0 * sW[lane * 2 + 1] + h1 * sW[(32 + lane) * 2 + 1]
               + a0 * sW[(64 + lane) * 2 + 1] + a1 * sW[(96 + lane) * 2 + 1];

    #pragma unroll
    for (int o = 16; o > 0; o >>= 1) {
        acc0 += __shfl_xor_sync(0xFFFFFFFFu, acc0, o);
        acc1 += __shfl_xor_sync(0xFFFFFFFFu, acc1, o);
    }
    if (lane == 0) {
        out[(long long)warp * DOUT + 0] = acc0 + sb[0];
        out[(long long)warp * DOUT + 1] = acc1 + sb[1];
    }
}

// ---------------------------------------------------------------------------
// kernel_launch
// Inputs (metadata order):
//   0 x [N*128] f32, 1 edge_index [2*E] int32 (int64 narrowed by harness),
//   2 env_edge_attr [E*128] f32, 3 act_edge_attr [E*64] f32,
//   4 W0 [256*64] f32, 5 b0 [64] f32, 6 W1 [128*2] f32, 7 b1 [2] f32.
// Output: [N*2] f32.
// ---------------------------------------------------------------------------
extern "C" void kernel_launch(void* const* d_in, const int* in_sizes, int n_in,
                              void* d_out, int out_size)
{
    const float* x   = (const float*)d_in[0];
    const int*   ei  = (const int*)d_in[1];
    const float* ea0 = (const float*)d_in[2];
    const float* ea1 = (const float*)d_in[3];
    const float* W0  = (const float*)d_in[4];
    const float* b0  = (const float*)d_in[5];
    const float* W1  = (const float*)d_in[6];
    const float* b1  = (const float*)d_in[7];
    float* out = (float*)d_out;

    const int N = in_sizes[0] / DIN;
    const int E = in_sizes[1] / 2;

    float *agg0_p, *agg1_p, *h_p, *cnt_p;
    cudaGetSymbolAddress((void**)&agg0_p, g_agg0);
    cudaGetSymbolAddress((void**)&agg1_p, g_agg1);
    cudaGetSymbolAddress((void**)&h_p,    g_h);
    cudaGetSymbolAddress((void**)&cnt_p,  g_cnt);

    // zero scratch
    cudaMemsetAsync(agg0_p, 0, (size_t)N * DIN * sizeof(float), 0);
    cudaMemsetAsync(agg1_p, 0, (size_t)N * HID * sizeof(float), 0);
    cudaMemsetAsync(cnt_p,  0, (size_t)N * sizeof(float), 0);

    // layer 0 scatter: warp per edge
    {
        int threads = 256;
        int warpsPerBlock = threads / 32;
        int blocks = (E + warpsPerBlock - 1) / warpsPerBlock;
        scatter0_kernel<<<blocks, threads>>>(x, ei, ea0, agg0_p, cnt_p, E);
    }

    // layer 0 dense
    {
        int threads = 256;
        int blocks = 2048;
        size_t smem = (size_t)(2 * DIN * HID + 4 * 2 * DIN) * sizeof(float); // 69632 B
        cudaFuncSetAttribute(layer0_mm_kernel,
                             cudaFuncAttributeMaxDynamicSharedMemorySize, (int)smem);
        layer0_mm_kernel<<<blocks, threads, smem>>>(x, agg0_p, cnt_p, W0, b0, h_p, N);
    }

    // layer 1 scatter
    {
        int threads = 256;
        int warpsPerBlock = threads / 32;
        int blocks = (E + warpsPerBlock - 1) / warpsPerBlock;
        scatter1_kernel<<<blocks, threads>>>(h_p, ei, ea1, agg1_p, E);
    }

    // layer 1 dense: warp per node
    {
        int threads = 256;
        int warpsPerBlock = threads / 32;
        int blocks = (N + warpsPerBlock - 1) / warpsPerBlock;
        layer1_mm_kernel<<<blocks, threads>>>(h_p, agg1_p, cnt_p, W1, b1, out, N);
    }
}

// round 3
// speedup vs baseline: 1.3101x; 1.3101x over previous
#include <cuda_runtime.h>
#include <cuda_bf16.h>
#include <stdint.h>

#define N_NODES 100000
#define E_EDGES 1600000
#define DIN 128
#define HID 64
#define DOUT 2

__device__ float g_agg0[(size_t)N_NODES * DIN];
__device__ float g_agg1[(size_t)N_NODES * HID];
__device__ float g_h[(size_t)N_NODES * HID];
__device__ float g_cnt[N_NODES];

// Vector reductions (sm_90+): one L2 transaction for 4 floats.
__device__ __forceinline__ void red_add_v4(float* addr, float4 v) {
    asm volatile("red.global.add.v4.f32 [%0], {%1,%2,%3,%4};"
                 :: "l"(addr), "f"(v.x), "f"(v.y), "f"(v.z), "f"(v.w) : "memory");
}

// ---------------------------------------------------------------------------
// Layer 0 scatter: one warp per edge, 32 lanes x float4, v4 reduction.
// ---------------------------------------------------------------------------
__global__ void scatter0_kernel(const float* __restrict__ x,
                                const int* __restrict__ ei,
                                const float* __restrict__ ea,
                                float* __restrict__ agg0,
                                float* __restrict__ cnt,
                                int E)
{
    int warp = (blockIdx.x * blockDim.x + threadIdx.x) >> 5;
    int lane = threadIdx.x & 31;
    if (warp >= E) return;

    int s = ei[warp];
    int d = ei[E + warp];

    const float4* xr = reinterpret_cast<const float4*>(x + (long long)s * DIN);
    const float4* er = reinterpret_cast<const float4*>(ea + (long long)warp * DIN);
    float4 xv = xr[lane];
    float4 ev = er[lane];

    float4 m = make_float4(xv.x * ev.x, xv.y * ev.y, xv.z * ev.z, xv.w * ev.w);
    red_add_v4(agg0 + (long long)d * DIN + lane * 4, m);

    if (lane == 0) atomicAdd(cnt + d, 1.0f);
}

// ---------------------------------------------------------------------------
// Layer 1 scatter: 2 edges per warp. Lanes 0-15 edge A, 16-31 edge B.
// Each lane covers 4 channels -> one v4 reduction. 64ch = 16 lanes x float4.
// ---------------------------------------------------------------------------
__global__ void scatter1_kernel(const float* __restrict__ h,
                                const int* __restrict__ ei,
                                const float* __restrict__ ea,
                                float* __restrict__ agg1,
                                int E)
{
    int warp = (blockIdx.x * blockDim.x + threadIdx.x) >> 5;
    int lane = threadIdx.x & 31;
    int e = warp * 2 + (lane >> 4);   // which edge this half-warp handles
    if (e >= E) return;
    int sub = lane & 15;              // 0..15, 4 channels each

    int s = ei[e];
    int d = ei[E + e];

    const float4* hr = reinterpret_cast<const float4*>(h + (long long)s * HID);
    const float4* er = reinterpret_cast<const float4*>(ea + (long long)e * HID);
    float4 hv = hr[sub];
    float4 ev = er[sub];

    float4 m = make_float4(hv.x * ev.x, hv.y * ev.y, hv.z * ev.z, hv.w * ev.w);
    red_add_v4(agg1 + (long long)d * HID + sub * 4, m);
}

// ---------------------------------------------------------------------------
// Layer 0 dense: h = relu(concat(x, agg0/cnt) @ W0 + b0)
// ---------------------------------------------------------------------------
__global__ void layer0_mm_kernel(const float* __restrict__ x,
                                 const float* __restrict__ agg0,
                                 const float* __restrict__ cnt,
                                 const float* __restrict__ W0,
                                 const float* __restrict__ b0,
                                 float* __restrict__ h,
                                 int N)
{
    extern __shared__ float sm[];
    float* sW = sm;                 // 256*64
    float* sF = sm + 2 * DIN * HID; // 4*256

    for (int i = threadIdx.x; i < 2 * DIN * HID; i += blockDim.x)
        sW[i] = W0[i];
    __syncthreads();

    int slot = threadIdx.x >> 6;   // 0..3
    int oc   = threadIdx.x & 63;
    float bias = b0[oc];

    for (int base = blockIdx.x * 4; base < N; base += gridDim.x * 4) {
        __syncthreads();
        for (int i = threadIdx.x; i < 4 * 2 * DIN; i += blockDim.x) {
            int nn = base + (i >> 8);
            int k  = i & 255;
            float v = 0.f;
            if (nn < N) {
                if (k < DIN) {
                    v = x[(long long)nn * DIN + k];
                } else {
                    float c = cnt[nn];
                    c = c < 1.f ? 1.f : c;
                    v = agg0[(long long)nn * DIN + (k - DIN)] * (1.0f / c);
                }
            }
            sF[i] = v;
        }
        __syncthreads();

        int node = base + slot;
        if (node < N) {
            const float* f = sF + slot * 2 * DIN;
            float acc = bias;
            #pragma unroll 8
            for (int k = 0; k < 2 * DIN; k++)
                acc = fmaf(f[k], sW[k * HID + oc], acc);
            h[(long long)node * HID + oc] = acc > 0.f ? acc : 0.f;
        }
    }
}

// ---------------------------------------------------------------------------
// Layer 1 dense: out = concat(h, agg1/cnt) @ W1 + b1, one warp per node.
// ---------------------------------------------------------------------------
__global__ void layer1_mm_kernel(const float* __restrict__ h,
                                 const float* __restrict__ agg1,
                                 const float* __restrict__ cnt,
                                 const float* __restrict__ W1,
                                 const float* __restrict__ b1,
                                 float* __restrict__ out,
                                 int N)
{
    __shared__ float sW[2 * HID * DOUT];
    __shared__ float sb[DOUT];
    for (int i = threadIdx.x; i < 2 * HID * DOUT; i += blockDim.x) sW[i] = W1[i];
    if (threadIdx.x < DOUT) sb[threadIdx.x] = b1[threadIdx.x];
    __syncthreads();

    int warp = (blockIdx.x * blockDim.x + threadIdx.x) >> 5;
    int lane = threadIdx.x & 31;
    if (warp >= N) return;

    float c = cnt[warp];
    float inv = 1.0f / (c < 1.f ? 1.f : c);

    long long rb = (long long)warp * HID;
    float h0 = h[rb + lane];
    float h1 = h[rb + 32 + lane];
    float a0 = agg1[rb + lane] * inv;
    float a1 = agg1[rb + 32 + lane] * inv;

    float acc0 = h0 * sW[lane * 2 + 0] + h1 * sW[(32 + lane) * 2 + 0]
               + a0 * sW[(64 + lane) * 2 + 0] + a1 * sW[(96 + lane) * 2 + 0];
    float acc1 = h0 * sW[lane * 2 + 1] + h1 * sW[(32 + lane) * 2 + 1]
               + a0 * sW[(64 + lane) * 2 + 1] + a1 * sW[(96 + lane) * 2 + 1];

    #pragma unroll
    for (int o = 16; o > 0; o >>= 1) {
        acc0 += __shfl_xor_sync(0xFFFFFFFFu, acc0, o);
        acc1 += __shfl_xor_sync(0xFFFFFFFFu, acc1, o);
    }
    if (lane == 0) {
        out[(long long)warp * DOUT + 0] = acc0 + sb[0];
        out[(long long)warp * DOUT + 1] = acc1 + sb[1];
    }
}

// ---------------------------------------------------------------------------
extern "C" void kernel_launch(void* const* d_in, const int* in_sizes, int n_in,
                              void* d_out, int out_size)
{
    const float* x   = (const float*)d_in[0];
    const int*   ei  = (const int*)d_in[1];
    const float* ea0 = (const float*)d_in[2];
    const float* ea1 = (const float*)d_in[3];
    const float* W0  = (const float*)d_in[4];
    const float* b0  = (const float*)d_in[5];
    const float* W1  = (const float*)d_in[6];
    const float* b1  = (const float*)d_in[7];
    float* out = (float*)d_out;

    const int N = in_sizes[0] / DIN;
    const int E = in_sizes[1] / 2;

    float *agg0_p, *agg1_p, *h_p, *cnt_p;
    cudaGetSymbolAddress((void**)&agg0_p, g_agg0);
    cudaGetSymbolAddress((void**)&agg1_p, g_agg1);
    cudaGetSymbolAddress((void**)&h_p,    g_h);
    cudaGetSymbolAddress((void**)&cnt_p,  g_cnt);

    cudaMemsetAsync(agg0_p, 0, (size_t)N * DIN * sizeof(float), 0);
    cudaMemsetAsync(agg1_p, 0, (size_t)N * HID * sizeof(float), 0);
    cudaMemsetAsync(cnt_p,  0, (size_t)N * sizeof(float), 0);

    // layer 0 scatter: warp per edge
    {
        int threads = 256;
        int blocks = (E + 7) / 8;
        scatter0_kernel<<<blocks, threads>>>(x, ei, ea0, agg0_p, cnt_p, E);
    }

    // layer 0 dense
    {
        int threads = 256;
        int blocks = 2048;
        size_t smem = (size_t)(2 * DIN * HID + 4 * 2 * DIN) * sizeof(float);
        cudaFuncSetAttribute(layer0_mm_kernel,
                             cudaFuncAttributeMaxDynamicSharedMemorySize, (int)smem);
        layer0_mm_kernel<<<blocks, threads, smem>>>(x, agg0_p, cnt_p, W0, b0, h_p, N);
    }

    // layer 1 scatter: 2 edges per warp
    {
        int threads = 256;
        int edgesPerBlock = (threads / 32) * 2;
        int blocks = (E + edgesPerBlock - 1) / edgesPerBlock;
        scatter1_kernel<<<blocks, threads>>>(h_p, ei, ea1, agg1_p, E);
    }

    // layer 1 dense: warp per node
    {
        int threads = 256;
        int blocks = (N + 7) / 8;
        layer1_mm_kernel<<<blocks, threads>>>(h_p, agg1_p, cnt_p, W1, b1, out, N);
    }
}